// round 6
// baseline (speedup 1.0000x reference)
#include <cuda_runtime.h>
#include <stdint.h>
#include <stdio.h>

// Problem constants
#define BATCH 16384
#define HID   512
#define ALPH  64
#define SEQL  256
#define BOSID 64
#define G4    2048            // 4*HID

// ---------------- device scratch (static, allowed) ----------------
__device__ float d_h[BATCH * HID];
__device__ float d_c[BATCH * HID];
__device__ float d_gates[BATCH * G4];          // 134 MB
__device__ float d_E[(ALPH + 1) * G4];         // embed @ w_ih^T + b_ih + b_hh
__device__ float d_logits[BATCH * ALPH];
__device__ unsigned d_keys[SEQL * 2];          // keys[t] = (y0, y1) of fold-in(t)
__device__ unsigned g_bar = 0;
__device__ unsigned g_gen = 0;

// ---------------- grid-wide barrier (all CTAs co-resident) ----------------
__device__ __forceinline__ void gsync() {
    __threadfence();          // release my writes (gpu scope)
    __syncthreads();
    if (threadIdx.x == 0) {
        unsigned nb = gridDim.x;
        unsigned gen = *(volatile unsigned*)&g_gen;
        if (atomicAdd(&g_bar, 1u) == nb - 1u) {
            atomicExch(&g_bar, 0u);
            __threadfence();
            atomicAdd(&g_gen, 1u);
        } else {
            while (*(volatile unsigned*)&g_gen == gen) __nanosleep(64);
        }
        __threadfence();      // acquire
    }
    __syncthreads();
}

// ---------------- threefry2x32 (bit-exact JAX) ----------------
__device__ __forceinline__ unsigned rotl32(unsigned v, int r) {
    return (v << r) | (v >> (32 - r));
}
__device__ __forceinline__ void tf_round(unsigned &x0, unsigned &x1, int r) {
    x0 += x1; x1 = rotl32(x1, r); x1 ^= x0;
}
__device__ __forceinline__ uint2 threefry2x32(unsigned k0, unsigned k1,
                                              unsigned x0, unsigned x1) {
    unsigned ks2 = k0 ^ k1 ^ 0x1BD11BDAu;
    x0 += k0; x1 += k1;
    tf_round(x0, x1, 13); tf_round(x0, x1, 15); tf_round(x0, x1, 26); tf_round(x0, x1, 6);
    x0 += k1; x1 += ks2 + 1u;
    tf_round(x0, x1, 17); tf_round(x0, x1, 29); tf_round(x0, x1, 16); tf_round(x0, x1, 24);
    x0 += ks2; x1 += k0 + 2u;
    tf_round(x0, x1, 13); tf_round(x0, x1, 15); tf_round(x0, x1, 26); tf_round(x0, x1, 6);
    x0 += k0; x1 += k1 + 3u;
    tf_round(x0, x1, 17); tf_round(x0, x1, 29); tf_round(x0, x1, 16); tf_round(x0, x1, 24);
    x0 += k1; x1 += ks2 + 4u;
    tf_round(x0, x1, 13); tf_round(x0, x1, 15); tf_round(x0, x1, 26); tf_round(x0, x1, 6);
    x0 += ks2; x1 += k0 + 5u;
    return make_uint2(x0, x1);
}

__device__ __forceinline__ float sigmoidf_(float x) { return 1.f / (1.f + expf(-x)); }

__device__ __forceinline__ float gumbel_from_bits(unsigned bits) {
    float u = __uint_as_float((bits >> 9) | 0x3f800000u) - 1.0f;
    u = fmaxf(1.17549435e-38f, u + 1.17549435e-38f);
    return -logf(-logf(u));
}

// partitionable (counter-mode) 32-bit random bits at flat counter f (< 2^32):
// block = (hi=0, lo=f); bits = o1 ^ o2
__device__ __forceinline__ unsigned pbits32(unsigned k0, unsigned k1, unsigned f) {
    uint2 y = threefry2x32(k0, k1, 0u, f);
    return y.x ^ y.y;
}

// ---------------- main GEMM tile: gates[m0:m0+128][n0:n0+128] = h @ w_hh^T ----
#define BM 128
#define BN 128
#define BKK 16

__device__ void gemm_tile(const float* __restrict__ W, int tile) {
    static __shared__ float As[2][BKK][BM];
    static __shared__ float Bs[2][BKK][BN];
    __syncthreads();   // protect smem from previous tile / phase

    const int n0 = (tile & (G4 / BN - 1)) * BN;
    const int m0 = (tile / (G4 / BN)) * BM;
    const int tid = threadIdx.x;
    const int ty = tid >> 4;
    const int tx = tid & 15;

    float acc[8][8];
#pragma unroll
    for (int i = 0; i < 8; i++)
#pragma unroll
        for (int j = 0; j < 8; j++) acc[i][j] = 0.f;

    const int rA0 = tid >> 2, sA0 = tid & 3;
    const int rA1 = (tid + 256) >> 2, sA1 = tid & 3;

    float4 la0, la1, lb0, lb1;
    {
        const float* Ap = d_h + (size_t)(m0)*HID;
        la0 = __ldcg((const float4*)&Ap[(size_t)rA0 * HID + sA0 * 4]);
        la1 = __ldcg((const float4*)&Ap[(size_t)rA1 * HID + sA1 * 4]);
        const float* Bp = W + (size_t)(n0)*HID;
        lb0 = *(const float4*)&Bp[(size_t)rA0 * HID + sA0 * 4];
        lb1 = *(const float4*)&Bp[(size_t)rA1 * HID + sA1 * 4];
        As[0][sA0 * 4 + 0][rA0] = la0.x; As[0][sA0 * 4 + 1][rA0] = la0.y;
        As[0][sA0 * 4 + 2][rA0] = la0.z; As[0][sA0 * 4 + 3][rA0] = la0.w;
        As[0][sA1 * 4 + 0][rA1] = la1.x; As[0][sA1 * 4 + 1][rA1] = la1.y;
        As[0][sA1 * 4 + 2][rA1] = la1.z; As[0][sA1 * 4 + 3][rA1] = la1.w;
        Bs[0][sA0 * 4 + 0][rA0] = lb0.x; Bs[0][sA0 * 4 + 1][rA0] = lb0.y;
        Bs[0][sA0 * 4 + 2][rA0] = lb0.z; Bs[0][sA0 * 4 + 3][rA0] = lb0.w;
        Bs[0][sA1 * 4 + 0][rA1] = lb1.x; Bs[0][sA1 * 4 + 1][rA1] = lb1.y;
        Bs[0][sA1 * 4 + 2][rA1] = lb1.z; Bs[0][sA1 * 4 + 3][rA1] = lb1.w;
    }
    __syncthreads();

    int cur = 0;
    const int NT = HID / BKK;  // 32
    for (int kt = 0; kt < NT; kt++) {
        if (kt + 1 < NT) {
            const int kb = (kt + 1) * BKK;
            const float* Ap = d_h + (size_t)(m0)*HID + kb;
            la0 = __ldcg((const float4*)&Ap[(size_t)rA0 * HID + sA0 * 4]);
            la1 = __ldcg((const float4*)&Ap[(size_t)rA1 * HID + sA1 * 4]);
            const float* Bp = W + (size_t)(n0)*HID + kb;
            lb0 = *(const float4*)&Bp[(size_t)rA0 * HID + sA0 * 4];
            lb1 = *(const float4*)&Bp[(size_t)rA1 * HID + sA1 * 4];
        }
#pragma unroll
        for (int kk = 0; kk < BKK; kk++) {
            float a[8], b[8];
            *(float4*)&a[0] = *(const float4*)&As[cur][kk][ty * 8];
            *(float4*)&a[4] = *(const float4*)&As[cur][kk][ty * 8 + 4];
            *(float4*)&b[0] = *(const float4*)&Bs[cur][kk][tx * 8];
            *(float4*)&b[4] = *(const float4*)&Bs[cur][kk][tx * 8 + 4];
#pragma unroll
            for (int i = 0; i < 8; i++)
#pragma unroll
                for (int j = 0; j < 8; j++) acc[i][j] += a[i] * b[j];
        }
        if (kt + 1 < NT) {
            int nxt = cur ^ 1;
            As[nxt][sA0 * 4 + 0][rA0] = la0.x; As[nxt][sA0 * 4 + 1][rA0] = la0.y;
            As[nxt][sA0 * 4 + 2][rA0] = la0.z; As[nxt][sA0 * 4 + 3][rA0] = la0.w;
            As[nxt][sA1 * 4 + 0][rA1] = la1.x; As[nxt][sA1 * 4 + 1][rA1] = la1.y;
            As[nxt][sA1 * 4 + 2][rA1] = la1.z; As[nxt][sA1 * 4 + 3][rA1] = la1.w;
            Bs[nxt][sA0 * 4 + 0][rA0] = lb0.x; Bs[nxt][sA0 * 4 + 1][rA0] = lb0.y;
            Bs[nxt][sA0 * 4 + 2][rA0] = lb0.z; Bs[nxt][sA0 * 4 + 3][rA0] = lb0.w;
            Bs[nxt][sA1 * 4 + 0][rA1] = lb1.x; Bs[nxt][sA1 * 4 + 1][rA1] = lb1.y;
            Bs[nxt][sA1 * 4 + 2][rA1] = lb1.z; Bs[nxt][sA1 * 4 + 3][rA1] = lb1.w;
            __syncthreads();
            cur = nxt;
        }
    }

#pragma unroll
    for (int i = 0; i < 8; i++) {
        float* Cp = d_gates + (size_t)(m0 + ty * 8 + i) * G4 + n0 + tx * 8;
        *(float4*)&Cp[0] = make_float4(acc[i][0], acc[i][1], acc[i][2], acc[i][3]);
        *(float4*)&Cp[4] = make_float4(acc[i][4], acc[i][5], acc[i][6], acc[i][7]);
    }
}

// ---------------- sample for a 64-row chunk (counter-mode threefry) --------
__device__ void sample_chunk(int ch, int t, int* s_tok, float* __restrict__ out) {
    const int b0 = ch * 64;
    const int wid = threadIdx.x >> 5;
    const int lane = threadIdx.x & 31;
    const unsigned k0 = __ldcg(&d_keys[2 * t]);
    const unsigned k1 = __ldcg(&d_keys[2 * t + 1]);

    for (int rr = 0; rr < 8; rr++) {
        const int lb = wid * 8 + rr;
        const int b = b0 + lb;

        const int a0 = lane, a1 = lane + 32;
        const unsigned f0 = (unsigned)b * ALPH + a0;   // flat counter
        const unsigned f1 = f0 + 32u;
        unsigned bits0 = pbits32(k0, k1, f0);
        unsigned bits1 = pbits32(k0, k1, f1);

        float l0 = d_logits[(size_t)b * ALPH + a0];
        float l1 = d_logits[(size_t)b * ALPH + a1];
        float z0 = l0 + gumbel_from_bits(bits0);
        float z1 = l1 + gumbel_from_bits(bits1);

        // argmax with first-index tie-break
        float v; int idx;
        if (z1 > z0) { v = z1; idx = a1; } else { v = z0; idx = a0; }
#pragma unroll
        for (int off = 16; off > 0; off >>= 1) {
            float vo = __shfl_down_sync(0xffffffffu, v, off);
            int io = __shfl_down_sync(0xffffffffu, idx, off);
            if (vo > v || (vo == v && io < idx)) { v = vo; idx = io; }
        }
        idx = __shfl_sync(0xffffffffu, idx, 0);

        // log_softmax at idx
        float m = fmaxf(l0, l1);
#pragma unroll
        for (int off = 16; off > 0; off >>= 1)
            m = fmaxf(m, __shfl_xor_sync(0xffffffffu, m, off));
        float s = expf(l0 - m) + expf(l1 - m);
#pragma unroll
        for (int off = 16; off > 0; off >>= 1)
            s += __shfl_xor_sync(0xffffffffu, s, off);

        float ltok = __shfl_sync(0xffffffffu, (idx < 32 ? l0 : l1), idx & 31);

        if (lane == 0) {
            s_tok[lb] = idx;
            out[(size_t)b * SEQL + t] = (float)idx;
            out[(size_t)BATCH * SEQL + b] += ltok - m - logf(s);
        }
    }
}

// ---------------- cell + head for a 64-row chunk ----------------
__device__ void cell_head(int ch, int use_tok, int has_gates, int czero,
                          const int* s_tok,
                          const float* __restrict__ hw, const float* __restrict__ hb) {
    const int b0 = ch * 64;
    const int tid = threadIdx.x;

    // cell: 64 rows x 512
    for (int e = tid; e < 64 * HID; e += 256) {
        int lr = e >> 9, k = e & (HID - 1);
        int b = b0 + lr;
        int tk = use_tok ? s_tok[lr] : BOSID;
        const float* Er = d_E + (size_t)tk * G4;
        float gi = __ldcg(&Er[k]);
        float gf = __ldcg(&Er[HID + k]);
        float gg = __ldcg(&Er[2 * HID + k]);
        float go = __ldcg(&Er[3 * HID + k]);
        if (has_gates) {
            const float* gr = d_gates + (size_t)b * G4;
            gi += __ldcg(&gr[k]);
            gf += __ldcg(&gr[HID + k]);
            gg += __ldcg(&gr[2 * HID + k]);
            go += __ldcg(&gr[3 * HID + k]);
        }
        float cc = czero ? 0.f : d_c[(size_t)b * HID + k];
        float c2 = sigmoidf_(gf) * cc + sigmoidf_(gi) * tanhf(gg);
        d_c[(size_t)b * HID + k] = c2;
        d_h[(size_t)b * HID + k] = sigmoidf_(go) * tanhf(c2);
    }
    __syncthreads();

    // head: logits[64x64] = h @ head_w^T + head_b
    static __shared__ float shh[64][65];
    static __shared__ float shw[64][65];
    const int ty = tid >> 4, tx = tid & 15;
    float acc[4][4];
#pragma unroll
    for (int i = 0; i < 4; i++)
#pragma unroll
        for (int j = 0; j < 4; j++) acc[i][j] = 0.f;

    for (int kc = 0; kc < HID; kc += 64) {
#pragma unroll
        for (int q = 0; q < 4; q++) {
            int fi = tid + q * 256;
            int row = fi >> 4, c4 = fi & 15;
            float4 v = *(const float4*)&d_h[(size_t)(b0 + row) * HID + kc + c4 * 4];
            shh[row][c4 * 4 + 0] = v.x; shh[row][c4 * 4 + 1] = v.y;
            shh[row][c4 * 4 + 2] = v.z; shh[row][c4 * 4 + 3] = v.w;
            float4 w = *(const float4*)&hw[(size_t)row * HID + kc + c4 * 4];
            shw[row][c4 * 4 + 0] = w.x; shw[row][c4 * 4 + 1] = w.y;
            shw[row][c4 * 4 + 2] = w.z; shw[row][c4 * 4 + 3] = w.w;
        }
        __syncthreads();
#pragma unroll 4
        for (int kk = 0; kk < 64; kk++) {
            float av[4], bv[4];
#pragma unroll
            for (int i = 0; i < 4; i++) av[i] = shh[ty * 4 + i][kk];
#pragma unroll
            for (int j = 0; j < 4; j++) bv[j] = shw[tx * 4 + j][kk];
#pragma unroll
            for (int i = 0; i < 4; i++)
#pragma unroll
                for (int j = 0; j < 4; j++) acc[i][j] += av[i] * bv[j];
        }
        __syncthreads();
    }
#pragma unroll
    for (int i = 0; i < 4; i++)
#pragma unroll
        for (int j = 0; j < 4; j++)
            d_logits[(size_t)(b0 + ty * 4 + i) * ALPH + tx * 4 + j] = acc[i][j] + hb[tx * 4 + j];
}

// ---------------- the one persistent kernel ----------------
__global__ __launch_bounds__(256, 2)
void k_all(const float* __restrict__ embed, const float* __restrict__ w_ih,
           const float* __restrict__ w_hh, const float* __restrict__ b_ih,
           const float* __restrict__ b_hh, const float* __restrict__ head_w,
           const float* __restrict__ head_b, float* __restrict__ out) {
    __shared__ int s_tok[64];
    const int tid = threadIdx.x;
    const unsigned gtid = blockIdx.x * 256u + tid;
    const unsigned nth = gridDim.x * 256u;

    // ---- phase 0: keys (partitionable split == per-index fold-in), logp, E ----
    if (blockIdx.x == 0 && tid < SEQL) {
        uint2 y = threefry2x32(0u, 42u, 0u, (unsigned)tid);  // keys[t] = full pair
        d_keys[2 * tid]     = y.x;
        d_keys[2 * tid + 1] = y.y;
    }
    for (unsigned i = gtid; i < BATCH; i += nth)
        out[(size_t)BATCH * SEQL + i] = 0.f;
    for (unsigned idx = gtid; idx < (ALPH + 1) * G4; idx += nth) {
        int t = idx / G4, j = idx % G4;
        const float* er = embed + t * HID;
        const float* wr = w_ih + (size_t)j * HID;
        float s = b_ih[j] + b_hh[j];
#pragma unroll 8
        for (int k = 0; k < HID; k++) s += __ldg(&er[k]) * __ldg(&wr[k]);
        d_E[idx] = s;
    }
    gsync();

    // ---- BOS step: h=c=0 -> gates = E[BOS]; then head ----
    for (int ch = blockIdx.x; ch < BATCH / 64; ch += gridDim.x) {
        cell_head(ch, /*use_tok*/0, /*has_gates*/0, /*czero*/1, s_tok, head_w, head_b);
        __syncthreads();
    }
    gsync();

    // ---- main loop ----
    for (int t = 0; t < SEQL; t++) {
        // phase A: recurrent GEMM gates = h_t @ w_hh^T (skipped after last sample)
        if (t < SEQL - 1) {
            for (int tile = blockIdx.x; tile < (BATCH / BM) * (G4 / BN); tile += gridDim.x)
                gemm_tile(w_hh, tile);
        }
        gsync();
        // phase B: sample tok_t; then cell+head -> logits_{t+1}
        for (int ch = blockIdx.x; ch < BATCH / 64; ch += gridDim.x) {
            sample_chunk(ch, t, s_tok, out);
            if (t < SEQL - 1) {
                __syncthreads();
                cell_head(ch, 1, 1, 0, s_tok, head_w, head_b);
            }
            __syncthreads();
        }
        gsync();
    }
}

// ---------------- launch ----------------
extern "C" void kernel_launch(void* const* d_in, const int* in_sizes, int n_in,
                              void* d_out, int out_size) {
    int off = (in_sizes[0] == (ALPH + 1) * HID) ? 0 : 1;
    const float* embed  = (const float*)d_in[off + 0];
    const float* w_ih   = (const float*)d_in[off + 1];
    const float* w_hh   = (const float*)d_in[off + 2];
    const float* b_ih   = (const float*)d_in[off + 3];
    const float* b_hh   = (const float*)d_in[off + 4];
    const float* head_w = (const float*)d_in[off + 5];
    const float* head_b = (const float*)d_in[off + 6];
    float* out = (float*)d_out;

    int dev = 0;
    cudaGetDevice(&dev);
    int nsm = 148;
    cudaDeviceGetAttribute(&nsm, cudaDevAttrMultiProcessorCount, dev);

    // 2 CTAs/SM guaranteed resident by __launch_bounds__(256, 2)
    k_all<<<nsm * 2, 256>>>(embed, w_ih, w_hh, b_ih, b_hh, head_w, head_b, out);
}